// round 11
// baseline (speedup 1.0000x reference)
#include <cuda_runtime.h>
#include <cuda_fp16.h>
#include <cstdint>

#define BATCH 8192
#define DIM   1024
#define H1V   8
#define H2V   4
#define OUTD  256
#define K2DIM 4096   // DIM*H2
#define EPSV  1e-5f
#define RG1   32
#define RG2   32

// ---------------- scratch (device globals; no allocation) ----------------
__device__ __half g_h2[(size_t)BATCH * K2DIM];   // 64 MB, h2 pre-BN in fp16
__device__ __half g_wfc[OUTD * K2DIM];           // 2 MB, Wfc in fp16
__device__ float  g_p1s[RG1 * DIM],  g_p1q[RG1 * DIM];
__device__ float  g_p2s[RG2 * K2DIM], g_p2q[RG2 * K2DIM];
__device__ float  g_a2[K2DIM], g_c2[K2DIM];

// ---------------- K1: merged Wfc->fp16 + per-column sums of x ----------------
// grid 768 x 256: blocks [0,256) do stats (cg = b&7, rg = b>>3), [256,768) convert Wfc.
__global__ void k_pre(const float* __restrict__ x, const float* __restrict__ Wfc) {
    int b = blockIdx.x, t = threadIdx.x;
    if (b < 256) {
        int cg = b & 7, rg = b >> 3;
        int cl = t & 31, rt = t >> 5;
        int d = cg * 128 + cl * 4;
        float4 s = make_float4(0.f, 0.f, 0.f, 0.f);
        float4 q = make_float4(0.f, 0.f, 0.f, 0.f);
        const float4* p = reinterpret_cast<const float4*>(
            x + (size_t)(rg * 256 + rt) * DIM + d);
#pragma unroll 8
        for (int i = 0; i < 32; i++) {
            float4 v = p[(size_t)i * 8 * (DIM / 4)];
            s.x += v.x; q.x = fmaf(v.x, v.x, q.x);
            s.y += v.y; q.y = fmaf(v.y, v.y, q.y);
            s.z += v.z; q.z = fmaf(v.z, v.z, q.z);
            s.w += v.w; q.w = fmaf(v.w, v.w, q.w);
        }
        __shared__ float rs[8][128], rq[8][128];
        rs[rt][cl * 4 + 0] = s.x; rq[rt][cl * 4 + 0] = q.x;
        rs[rt][cl * 4 + 1] = s.y; rq[rt][cl * 4 + 1] = q.y;
        rs[rt][cl * 4 + 2] = s.z; rq[rt][cl * 4 + 2] = q.z;
        rs[rt][cl * 4 + 3] = s.w; rq[rt][cl * 4 + 3] = q.w;
        __syncthreads();
        if (t < 128) {
            float ss = 0.f, qq = 0.f;
#pragma unroll
            for (int r = 0; r < 8; r++) { ss += rs[r][t]; qq += rq[r][t]; }
            g_p1s[rg * DIM + cg * 128 + t] = ss;
            g_p1q[rg * DIM + cg * 128 + t] = qq;
        }
    } else {
        // Wfc fp32 -> fp16: 512 blocks x 256 threads x 8 elems = 1048576
        int i = (b - 256) * 2048 + t * 8;
        float4 v0 = *reinterpret_cast<const float4*>(Wfc + i);
        float4 v1 = *reinterpret_cast<const float4*>(Wfc + i + 4);
        __half2 h0 = __floats2half2_rn(v0.x, v0.y);
        __half2 h1 = __floats2half2_rn(v0.z, v0.w);
        __half2 h2 = __floats2half2_rn(v1.x, v1.y);
        __half2 h3 = __floats2half2_rn(v1.z, v1.w);
        uint4 pk;
        pk.x = *reinterpret_cast<uint32_t*>(&h0);
        pk.y = *reinterpret_cast<uint32_t*>(&h1);
        pk.z = *reinterpret_cast<uint32_t*>(&h2);
        pk.w = *reinterpret_cast<uint32_t*>(&h3);
        *reinterpret_cast<uint4*>(g_wfc + i) = pk;
    }
}

// ---------------- K2: fin1 prologue + fused y1 -> h2 ----------------
// grid (16, 32), block 256, 3 CTAs/SM target.
__global__ void __launch_bounds__(256, 3)
k_layer2(const float* __restrict__ x, const float* __restrict__ W2,
         const float* __restrict__ W1, const float* __restrict__ g1,
         const float* __restrict__ be1) {
    int cg = blockIdx.x, rg = blockIdx.y, t = threadIdx.x;
    int dl = t & 63, rt = t >> 6;
    int d = cg * 64 + dl;

    __shared__ float sa[512], sc[512], sw[2048];

    // fin1 prologue: 64 threads each finalize one d (affine coeffs into smem)
    if (t < 64) {
        int dd = cg * 64 + t;
        float s = 0.f, q = 0.f;
#pragma unroll
        for (int r = 0; r < RG1; r++) { s += g_p1s[r * DIM + dd]; q += g_p1q[r * DIM + dd]; }
        float mx = s * (1.f / BATCH);
        float vx = fmaxf(q * (1.f / BATCH) - mx * mx, 0.f);
#pragma unroll
        for (int i = 0; i < H1V; i++) {
            int c = dd * H1V + i;
            float w = W1[c];
            float a = g1[c] * w * rsqrtf(fmaf(w * w, vx, EPSV));
            sa[t * 8 + i] = a;
            sc[t * 8 + i] = be1[c] - a * mx;   // b1 cancels inside BN
        }
    }
    for (int i = t; i < 2048; i += 256) { sw[i] = W2[cg * 2048 + i]; }
    __syncthreads();

    float a1r[8], c1r[8], w2r[4][8];
#pragma unroll
    for (int i = 0; i < 8; i++) { a1r[i] = sa[dl * 8 + i]; c1r[i] = sc[dl * 8 + i]; }
#pragma unroll
    for (int o = 0; o < 4; o++)
#pragma unroll
        for (int i = 0; i < 8; i++) w2r[o][i] = sw[dl * 32 + o * 8 + i];

    float s[4] = {0, 0, 0, 0}, q[4] = {0, 0, 0, 0};
    const int rbase = rg * 256 + rt;

#pragma unroll 1
    for (int it = 0; it < 64; it += 4) {
        float xv[4];
#pragma unroll
        for (int u = 0; u < 4; u++)
            xv[u] = x[(size_t)(rbase + (it + u) * 4) * DIM + d];
#pragma unroll
        for (int u = 0; u < 4; u++) {
            int r = rbase + (it + u) * 4;
            float y[8];
#pragma unroll
            for (int i = 0; i < 8; i++) y[i] = fmaxf(fmaf(a1r[i], xv[u], c1r[i]), 0.f);
            float h[4];
#pragma unroll
            for (int o = 0; o < 4; o++) {
                float acc = 0.f;
#pragma unroll
                for (int i = 0; i < 8; i++) acc = fmaf(w2r[o][i], y[i], acc);
                h[o] = acc;
                s[o] += acc;
                q[o] = fmaf(acc, acc, q[o]);
            }
            __half2 h01 = __floats2half2_rn(h[0], h[1]);
            __half2 h23 = __floats2half2_rn(h[2], h[3]);
            uint2 pk;
            pk.x = *reinterpret_cast<uint32_t*>(&h01);
            pk.y = *reinterpret_cast<uint32_t*>(&h23);
            *reinterpret_cast<uint2*>(g_h2 + (size_t)r * K2DIM + d * 4) = pk;
        }
    }

    __shared__ float red[4][64][8];
#pragma unroll
    for (int o = 0; o < 4; o++) { red[rt][dl][o] = s[o]; red[rt][dl][4 + o] = q[o]; }
    __syncthreads();
    if (t < 64) {
#pragma unroll
        for (int o = 0; o < 4; o++) {
            float ss = red[0][t][o] + red[1][t][o] + red[2][t][o] + red[3][t][o];
            float qq = red[0][t][4 + o] + red[1][t][4 + o] + red[2][t][4 + o] + red[3][t][4 + o];
            int c = (cg * 64 + t) * 4 + o;
            g_p2s[rg * K2DIM + c] = ss;
            g_p2q[rg * K2DIM + c] = qq;
        }
    }
}

// ---------------- K3: finalize layer-2 affine coefficients ----------------
__global__ void k_fin2(const float* __restrict__ g2, const float* __restrict__ be2) {
    int c = blockIdx.x * 256 + threadIdx.x;
    float s = 0.f, q = 0.f;
#pragma unroll
    for (int r = 0; r < RG2; r++) { s += g_p2s[r * K2DIM + c]; q += g_p2q[r * K2DIM + c]; }
    float mu = s * (1.f / BATCH);
    float var = fmaxf(q * (1.f / BATCH) - mu * mu, 0.f);
    float a = g2[c] * rsqrtf(var + EPSV);
    g_a2[c] = a;
    g_c2[c] = be2[c] - a * mu;
}

// ---------------- K4: out = relu(a2*h2+c2) @ Wfc^T + bfc (fp16 mma.sync) ----------------
__device__ __forceinline__ void ldsm_x4(uint32_t& r0, uint32_t& r1, uint32_t& r2, uint32_t& r3,
                                        uint32_t addr) {
    asm volatile("ldmatrix.sync.aligned.m8n8.x4.shared.b16 {%0,%1,%2,%3}, [%4];"
                 : "=r"(r0), "=r"(r1), "=r"(r2), "=r"(r3) : "r"(addr));
}
__device__ __forceinline__ void mma16816(float* c, const uint32_t a[4], uint32_t b0, uint32_t b1) {
    asm volatile(
        "mma.sync.aligned.m16n8k16.row.col.f32.f16.f16.f32 "
        "{%0,%1,%2,%3},{%4,%5,%6,%7},{%8,%9},{%0,%1,%2,%3};"
        : "+f"(c[0]), "+f"(c[1]), "+f"(c[2]), "+f"(c[3])
        : "r"(a[0]), "r"(a[1]), "r"(a[2]), "r"(a[3]), "r"(b0), "r"(b1));
}

#define AS_ELEMS (2 * 64 * 72)
#define BS_ELEMS (2 * 256 * 72)
#define GEMM_SMEM ((AS_ELEMS + BS_ELEMS) * 2 + 2 * K2DIM * 4)   // 124928 B

__global__ void __launch_bounds__(256, 1)
k_gemm(const float* __restrict__ bfc, float* __restrict__ out) {
    extern __shared__ char smraw[];
    __half* As = reinterpret_cast<__half*>(smraw);       // [2][64][72]
    __half* Bs = As + AS_ELEMS;                          // [2][256][72]
    float* a2s = reinterpret_cast<float*>(Bs + BS_ELEMS);
    float* c2s = a2s + K2DIM;

    const int t = threadIdx.x;
    const int bm = blockIdx.x * 64;
    const int warp = t >> 5, lane = t & 31;
    const int wm = warp >> 2, wn = warp & 3;             // warp tile: 32(m) x 64(n)

    for (int i = t; i < K2DIM; i += 256) { a2s[i] = g_a2[i]; c2s[i] = g_c2[i]; }

    const int arow = t >> 2, akoff = (t & 3) * 16;       // A: 64 rows x 64 k halves
    const __half* Agp = g_h2 + (size_t)(bm + arow) * K2DIM + akoff;
    const __half* Bgp = g_wfc + (size_t)t * K2DIM;       // B: row n = t

    float acc[2][8][4];
#pragma unroll
    for (int a = 0; a < 2; a++)
#pragma unroll
        for (int b = 0; b < 8; b++)
#pragma unroll
            for (int c = 0; c < 4; c++) acc[a][b][c] = 0.f;

    uint4 av[2], bv[8];

    auto store_chunk = [&](int buf, int kbase) {
        __half* ad = As + buf * (64 * 72) + arow * 72 + akoff;
#pragma unroll
        for (int j = 0; j < 2; j++) {
            uint4 v = av[j];
            __half2* hp = reinterpret_cast<__half2*>(&v);
            int kb = kbase + akoff + j * 8;
#pragma unroll
            for (int e = 0; e < 4; e++) {
                float2 f = __half22float2(hp[e]);
                int k = kb + e * 2;
                f.x = fmaxf(fmaf(a2s[k], f.x, c2s[k]), 0.f);
                f.y = fmaxf(fmaf(a2s[k + 1], f.y, c2s[k + 1]), 0.f);
                hp[e] = __floats2half2_rn(f.x, f.y);
            }
            *reinterpret_cast<uint4*>(ad + j * 8) = v;
        }
        __half* bd = Bs + buf * (256 * 72) + t * 72;
#pragma unroll
        for (int j = 0; j < 8; j++) *reinterpret_cast<uint4*>(bd + j * 8) = bv[j];
    };

    // prologue: chunk 0
    av[0] = *reinterpret_cast<const uint4*>(Agp);
    av[1] = *reinterpret_cast<const uint4*>(Agp + 8);
#pragma unroll
    for (int j = 0; j < 8; j++) bv[j] = *reinterpret_cast<const uint4*>(Bgp + j * 8);
    __syncthreads();                 // a2s/c2s ready
    store_chunk(0, 0);
    __syncthreads();

    const int a_lrow = lane & 15;
    const int a_ksel = ((lane >> 4) & 1) << 3;
    const int b_lrow = (lane & 7) + ((lane & 16) >> 1);
    const int b_ksel = lane & 8;

    for (int kc = 0; kc < 64; kc++) {
        int cur = kc & 1;
        if (kc < 63) {
            const __half* ag = Agp + (kc + 1) * 64;
            av[0] = *reinterpret_cast<const uint4*>(ag);
            av[1] = *reinterpret_cast<const uint4*>(ag + 8);
            const __half* bg = Bgp + (kc + 1) * 64;
#pragma unroll
            for (int j = 0; j < 8; j++) bv[j] = *reinterpret_cast<const uint4*>(bg + j * 8);
        }
        const __half* Ac = As + cur * (64 * 72);
        const __half* Bc = Bs + cur * (256 * 72);
#pragma unroll
        for (int ks = 0; ks < 4; ks++) {
            int kb = ks * 16;
            uint32_t af[2][4];
#pragma unroll
            for (int mt = 0; mt < 2; mt++) {
                int row = wm * 32 + mt * 16 + a_lrow;
                uint32_t addr = (uint32_t)__cvta_generic_to_shared(Ac + row * 72 + kb + a_ksel);
                ldsm_x4(af[mt][0], af[mt][1], af[mt][2], af[mt][3], addr);
            }
#pragma unroll
            for (int p = 0; p < 4; p++) {
                int nrow = wn * 64 + p * 16 + b_lrow;
                uint32_t addr = (uint32_t)__cvta_generic_to_shared(Bc + nrow * 72 + kb + b_ksel);
                uint32_t b0, b1, b2, b3;
                ldsm_x4(b0, b1, b2, b3, addr);
#pragma unroll
                for (int mt = 0; mt < 2; mt++) {
                    mma16816(acc[mt][2 * p], af[mt], b0, b1);
                    mma16816(acc[mt][2 * p + 1], af[mt], b2, b3);
                }
            }
        }
        if (kc < 63) store_chunk(1 - cur, (kc + 1) * 64);
        __syncthreads();
    }

    // epilogue
#pragma unroll
    for (int mt = 0; mt < 2; mt++) {
        int r0 = bm + wm * 32 + mt * 16 + (lane >> 2);
#pragma unroll
        for (int nt = 0; nt < 8; nt++) {
            int cc = wn * 64 + nt * 8 + ((lane & 3) << 1);
            float bl = bfc[cc], bh = bfc[cc + 1];
            float2 v0 = make_float2(acc[mt][nt][0] + bl, acc[mt][nt][1] + bh);
            float2 v1 = make_float2(acc[mt][nt][2] + bl, acc[mt][nt][3] + bh);
            *reinterpret_cast<float2*>(out + (size_t)r0 * OUTD + cc) = v0;
            *reinterpret_cast<float2*>(out + (size_t)(r0 + 8) * OUTD + cc) = v1;
        }
    }
}

// ---------------- launch ----------------
extern "C" void kernel_launch(void* const* d_in, const int* in_sizes, int n_in,
                              void* d_out, int out_size) {
    const float* x   = (const float*)d_in[0];
    const float* W1  = (const float*)d_in[1];
    const float* g1  = (const float*)d_in[3];
    const float* be1 = (const float*)d_in[4];
    const float* W2  = (const float*)d_in[5];
    const float* g2  = (const float*)d_in[7];
    const float* be2 = (const float*)d_in[8];
    const float* Wfc = (const float*)d_in[9];
    const float* bfc = (const float*)d_in[10];
    float* out = (float*)d_out;

    cudaFuncSetAttribute(k_gemm, cudaFuncAttributeMaxDynamicSharedMemorySize, GEMM_SMEM);

    k_pre<<<768, 256>>>(x, Wfc);
    k_layer2<<<dim3(16, 32), 256>>>(x, W2, W1, g1, be1);
    k_fin2<<<16, 256>>>(g2, be2);
    k_gemm<<<128, 256, GEMM_SMEM>>>(bfc, out);
}

// round 13
// speedup vs baseline: 1.3324x; 1.3324x over previous
#include <cuda_runtime.h>
#include <cuda_fp16.h>
#include <cstdint>

#define BATCH 8192
#define DIM   1024
#define H1V   8
#define H2V   4
#define OUTD  256
#define K2DIM 4096   // DIM*H2
#define EPSV  1e-5f
#define RG1   32
#define RG2   32

// ---------------- scratch (device globals; no allocation) ----------------
__device__ __half g_h2[(size_t)BATCH * K2DIM];   // 64 MB, h2 pre-BN in fp16
// Wfc pre-swizzled into mma.m16n8k16 B-fragment order:
// entry i: kt = i>>10, nt = (i>>5)&31, lane = i&31
//   .x = half2( Wfc[n][k0], Wfc[n][k0+1] ), .y = half2( Wfc[n][k0+8], Wfc[n][k0+9] )
//   with n = nt*8 + lane/4, k0 = kt*16 + (lane%4)*2
__device__ uint2  g_wfcB[256 * 32 * 32];         // 2 MB
__device__ float  g_p1s[RG1 * DIM],  g_p1q[RG1 * DIM];
__device__ float  g_p2s[RG2 * K2DIM], g_p2q[RG2 * K2DIM];
__device__ float  g_a2[K2DIM], g_c2[K2DIM];

// ---------------- K1: merged Wfc fragment-swizzle + per-column sums of x ----------------
// grid 1280 x 256: blocks [0,256) stats; [256,1280) build g_wfcB.
__global__ void k_pre(const float* __restrict__ x, const float* __restrict__ Wfc) {
    int b = blockIdx.x, t = threadIdx.x;
    if (b < 256) {
        int cg = b & 7, rg = b >> 3;
        int cl = t & 31, rt = t >> 5;
        int d = cg * 128 + cl * 4;
        float4 s = make_float4(0.f, 0.f, 0.f, 0.f);
        float4 q = make_float4(0.f, 0.f, 0.f, 0.f);
        const float4* p = reinterpret_cast<const float4*>(
            x + (size_t)(rg * 256 + rt) * DIM + d);
#pragma unroll 8
        for (int i = 0; i < 32; i++) {
            float4 v = p[(size_t)i * 8 * (DIM / 4)];
            s.x += v.x; q.x = fmaf(v.x, v.x, q.x);
            s.y += v.y; q.y = fmaf(v.y, v.y, q.y);
            s.z += v.z; q.z = fmaf(v.z, v.z, q.z);
            s.w += v.w; q.w = fmaf(v.w, v.w, q.w);
        }
        __shared__ float rs[8][128], rq[8][128];
        rs[rt][cl * 4 + 0] = s.x; rq[rt][cl * 4 + 0] = q.x;
        rs[rt][cl * 4 + 1] = s.y; rq[rt][cl * 4 + 1] = q.y;
        rs[rt][cl * 4 + 2] = s.z; rq[rt][cl * 4 + 2] = q.z;
        rs[rt][cl * 4 + 3] = s.w; rq[rt][cl * 4 + 3] = q.w;
        __syncthreads();
        if (t < 128) {
            float ss = 0.f, qq = 0.f;
#pragma unroll
            for (int r = 0; r < 8; r++) { ss += rs[r][t]; qq += rq[r][t]; }
            g_p1s[rg * DIM + cg * 128 + t] = ss;
            g_p1q[rg * DIM + cg * 128 + t] = qq;
        }
    } else {
        int i = (b - 256) * 256 + t;              // [0, 262144)
        int lane = i & 31, nt = (i >> 5) & 31, kt = i >> 10;
        int n = nt * 8 + (lane >> 2);
        int k0 = kt * 16 + (lane & 3) * 2;
        const float* wr = Wfc + (size_t)n * K2DIM + k0;
        __half2 b0 = __floats2half2_rn(wr[0], wr[1]);
        __half2 b1 = __floats2half2_rn(wr[8], wr[9]);
        uint2 pk;
        pk.x = *reinterpret_cast<uint32_t*>(&b0);
        pk.y = *reinterpret_cast<uint32_t*>(&b1);
        g_wfcB[i] = pk;
    }
}

// ---------------- K2: fin1 prologue + fused y1 -> h2 ----------------
__global__ void __launch_bounds__(256)
k_layer2(const float* __restrict__ x, const float* __restrict__ W2,
         const float* __restrict__ W1, const float* __restrict__ g1,
         const float* __restrict__ be1) {
    int cg = blockIdx.x, rg = blockIdx.y, t = threadIdx.x;
    int dl = t & 63, rt = t >> 6;
    int d = cg * 64 + dl;

    __shared__ float sa[512], sc[512], sw[2048];

    if (t < 64) {
        int dd = cg * 64 + t;
        float s = 0.f, q = 0.f;
#pragma unroll
        for (int r = 0; r < RG1; r++) { s += g_p1s[r * DIM + dd]; q += g_p1q[r * DIM + dd]; }
        float mx = s * (1.f / BATCH);
        float vx = fmaxf(q * (1.f / BATCH) - mx * mx, 0.f);
#pragma unroll
        for (int i = 0; i < H1V; i++) {
            int c = dd * H1V + i;
            float w = W1[c];
            float a = g1[c] * w * rsqrtf(fmaf(w * w, vx, EPSV));
            sa[t * 8 + i] = a;
            sc[t * 8 + i] = be1[c] - a * mx;   // b1 cancels inside BN
        }
    }
    for (int i = t; i < 2048; i += 256) { sw[i] = W2[cg * 2048 + i]; }
    __syncthreads();

    float a1r[8], c1r[8], w2r[4][8];
#pragma unroll
    for (int i = 0; i < 8; i++) { a1r[i] = sa[dl * 8 + i]; c1r[i] = sc[dl * 8 + i]; }
#pragma unroll
    for (int o = 0; o < 4; o++)
#pragma unroll
        for (int i = 0; i < 8; i++) w2r[o][i] = sw[dl * 32 + o * 8 + i];

    float s[4] = {0, 0, 0, 0}, q[4] = {0, 0, 0, 0};
    const int rbase = rg * 256 + rt;

#pragma unroll 1
    for (int it = 0; it < 64; it += 4) {
        float xv[4];
#pragma unroll
        for (int u = 0; u < 4; u++)
            xv[u] = x[(size_t)(rbase + (it + u) * 4) * DIM + d];
#pragma unroll
        for (int u = 0; u < 4; u++) {
            int r = rbase + (it + u) * 4;
            float y[8];
#pragma unroll
            for (int i = 0; i < 8; i++) y[i] = fmaxf(fmaf(a1r[i], xv[u], c1r[i]), 0.f);
            float h[4];
#pragma unroll
            for (int o = 0; o < 4; o++) {
                float acc = 0.f;
#pragma unroll
                for (int i = 0; i < 8; i++) acc = fmaf(w2r[o][i], y[i], acc);
                h[o] = acc;
                s[o] += acc;
                q[o] = fmaf(acc, acc, q[o]);
            }
            __half2 h01 = __floats2half2_rn(h[0], h[1]);
            __half2 h23 = __floats2half2_rn(h[2], h[3]);
            uint2 pk;
            pk.x = *reinterpret_cast<uint32_t*>(&h01);
            pk.y = *reinterpret_cast<uint32_t*>(&h23);
            *reinterpret_cast<uint2*>(g_h2 + (size_t)r * K2DIM + d * 4) = pk;
        }
    }

    __shared__ float red[4][64][8];
#pragma unroll
    for (int o = 0; o < 4; o++) { red[rt][dl][o] = s[o]; red[rt][dl][4 + o] = q[o]; }
    __syncthreads();
    if (t < 64) {
#pragma unroll
        for (int o = 0; o < 4; o++) {
            float ss = red[0][t][o] + red[1][t][o] + red[2][t][o] + red[3][t][o];
            float qq = red[0][t][4 + o] + red[1][t][4 + o] + red[2][t][4 + o] + red[3][t][4 + o];
            int c = (cg * 64 + t) * 4 + o;
            g_p2s[rg * K2DIM + c] = ss;
            g_p2q[rg * K2DIM + c] = qq;
        }
    }
}

// ---------------- K3: finalize layer-2 affine coefficients ----------------
__global__ void k_fin2(const float* __restrict__ g2, const float* __restrict__ be2) {
    int c = blockIdx.x * 256 + threadIdx.x;
    float s = 0.f, q = 0.f;
#pragma unroll
    for (int r = 0; r < RG2; r++) { s += g_p2s[r * K2DIM + c]; q += g_p2q[r * K2DIM + c]; }
    float mu = s * (1.f / BATCH);
    float var = fmaxf(q * (1.f / BATCH) - mu * mu, 0.f);
    float a = g2[c] * rsqrtf(var + EPSV);
    g_a2[c] = a;
    g_c2[c] = be2[c] - a * mu;
}

// ---------------- K4: out = relu(a2*h2+c2) @ Wfc^T + bfc ----------------
// A via smem (transform fused into STS); B streamed gmem->reg in fragment order.
__device__ __forceinline__ void ldsm_x4(uint32_t& r0, uint32_t& r1, uint32_t& r2, uint32_t& r3,
                                        uint32_t addr) {
    asm volatile("ldmatrix.sync.aligned.m8n8.x4.shared.b16 {%0,%1,%2,%3}, [%4];"
                 : "=r"(r0), "=r"(r1), "=r"(r2), "=r"(r3) : "r"(addr));
}
__device__ __forceinline__ void mma16816(float* c, const uint32_t a[4], uint32_t b0, uint32_t b1) {
    asm volatile(
        "mma.sync.aligned.m16n8k16.row.col.f32.f16.f16.f32 "
        "{%0,%1,%2,%3},{%4,%5,%6,%7},{%8,%9},{%0,%1,%2,%3};"
        : "+f"(c[0]), "+f"(c[1]), "+f"(c[2]), "+f"(c[3])
        : "r"(a[0]), "r"(a[1]), "r"(a[2]), "r"(a[3]), "r"(b0), "r"(b1));
}

#define AS_ELEMS (2 * 64 * 72)                       // 2 stages x 64 rows x 72 halves
#define GEMM_SMEM (AS_ELEMS * 2 + 2 * K2DIM * 4)     // 18432 + 32768 = 51200 B

__global__ void __launch_bounds__(256, 2)
k_gemm(const float* __restrict__ bfc, float* __restrict__ out) {
    extern __shared__ char smraw[];
    __half* As = reinterpret_cast<__half*>(smraw);       // [2][64][72]
    float* a2s = reinterpret_cast<float*>(As + AS_ELEMS);
    float* c2s = a2s + K2DIM;

    const int t = threadIdx.x;
    const int bm = blockIdx.x * 64;
    const int warp = t >> 5, lane = t & 31;
    const int wm = warp >> 2, wn = warp & 3;             // warp tile: 32(m) x 64(n)

    for (int i = t; i < K2DIM; i += 256) { a2s[i] = g_a2[i]; c2s[i] = g_c2[i]; }

    const int arow = t >> 2, akoff = (t & 3) * 16;       // A: 4 threads/row, 16 halves each
    const __half* Agp = g_h2 + (size_t)(bm + arow) * K2DIM + akoff;

    float acc[2][8][4];
#pragma unroll
    for (int a = 0; a < 2; a++)
#pragma unroll
        for (int b = 0; b < 8; b++)
#pragma unroll
            for (int c = 0; c < 4; c++) acc[a][b][c] = 0.f;

    uint4 av[2];

    auto store_chunk = [&](int buf, int kbase) {
        __half* ad = As + buf * (64 * 72) + arow * 72 + akoff;
#pragma unroll
        for (int j = 0; j < 2; j++) {
            uint4 v = av[j];
            __half2* hp = reinterpret_cast<__half2*>(&v);
            int kb = kbase + akoff + j * 8;
#pragma unroll
            for (int e = 0; e < 4; e++) {
                float2 f = __half22float2(hp[e]);
                int k = kb + e * 2;
                f.x = fmaxf(fmaf(a2s[k], f.x, c2s[k]), 0.f);
                f.y = fmaxf(fmaf(a2s[k + 1], f.y, c2s[k + 1]), 0.f);
                hp[e] = __floats2half2_rn(f.x, f.y);
            }
            *reinterpret_cast<uint4*>(ad + j * 8) = v;
        }
    };

    // B fragment stream state: stage s = global 16-k tile index (0..255)
    const uint2* Bbase = g_wfcB + (wn * 8) * 32 + lane;  // + s*1024 + nt*32
    uint2 bb[2][8];
#pragma unroll
    for (int nt = 0; nt < 8; nt++) bb[0][nt] = Bbase[nt * 32];   // s = 0

    // prologue: A chunk 0
    av[0] = *reinterpret_cast<const uint4*>(Agp);
    av[1] = *reinterpret_cast<const uint4*>(Agp + 8);
    __syncthreads();                 // a2s/c2s ready
    store_chunk(0, 0);
    __syncthreads();

    const int a_lrow = lane & 15;
    const int a_ksel = ((lane >> 4) & 1) << 3;

    for (int kc = 0; kc < 64; kc++) {
        int cur = kc & 1;
        // prefetch next A chunk (gmem)
        if (kc < 63) {
            const __half* ag = Agp + (kc + 1) * 64;
            av[0] = *reinterpret_cast<const uint4*>(ag);
            av[1] = *reinterpret_cast<const uint4*>(ag + 8);
        }
        const __half* Ac = As + cur * (64 * 72);
#pragma unroll
        for (int ks = 0; ks < 4; ks++) {
            int s = kc * 4 + ks;
            int bcur = s & 1;
            // prefetch next B fragment set (L2)
            if (s < 255) {
                const uint2* bp = Bbase + (size_t)(s + 1) * 1024;
#pragma unroll
                for (int nt = 0; nt < 8; nt++) bb[bcur ^ 1][nt] = bp[nt * 32];
            }
            int kb = ks * 16;
            uint32_t af[2][4];
#pragma unroll
            for (int mt = 0; mt < 2; mt++) {
                int row = wm * 32 + mt * 16 + a_lrow;
                uint32_t addr = (uint32_t)__cvta_generic_to_shared(Ac + row * 72 + kb + a_ksel);
                ldsm_x4(af[mt][0], af[mt][1], af[mt][2], af[mt][3], addr);
            }
#pragma unroll
            for (int nt = 0; nt < 8; nt++) {
                uint32_t b0 = bb[bcur][nt].x, b1 = bb[bcur][nt].y;
#pragma unroll
                for (int mt = 0; mt < 2; mt++)
                    mma16816(acc[mt][nt], af[mt], b0, b1);
            }
        }
        if (kc < 63) store_chunk(1 - cur, (kc + 1) * 64);
        __syncthreads();
    }

    // epilogue
#pragma unroll
    for (int mt = 0; mt < 2; mt++) {
        int r0 = bm + wm * 32 + mt * 16 + (lane >> 2);
#pragma unroll
        for (int nt = 0; nt < 8; nt++) {
            int cc = wn * 64 + nt * 8 + ((lane & 3) << 1);
            float bl = __ldg(bfc + cc), bh = __ldg(bfc + cc + 1);
            float2 v0 = make_float2(acc[mt][nt][0] + bl, acc[mt][nt][1] + bh);
            float2 v1 = make_float2(acc[mt][nt][2] + bl, acc[mt][nt][3] + bh);
            *reinterpret_cast<float2*>(out + (size_t)r0 * OUTD + cc) = v0;
            *reinterpret_cast<float2*>(out + (size_t)(r0 + 8) * OUTD + cc) = v1;
        }
    }
}

// ---------------- launch ----------------
extern "C" void kernel_launch(void* const* d_in, const int* in_sizes, int n_in,
                              void* d_out, int out_size) {
    const float* x   = (const float*)d_in[0];
    const float* W1  = (const float*)d_in[1];
    const float* g1  = (const float*)d_in[3];
    const float* be1 = (const float*)d_in[4];
    const float* W2  = (const float*)d_in[5];
    const float* g2  = (const float*)d_in[7];
    const float* be2 = (const float*)d_in[8];
    const float* Wfc = (const float*)d_in[9];
    const float* bfc = (const float*)d_in[10];
    float* out = (float*)d_out;

    cudaFuncSetAttribute(k_gemm, cudaFuncAttributeMaxDynamicSharedMemorySize, GEMM_SMEM);

    k_pre<<<1280, 256>>>(x, Wfc);
    k_layer2<<<dim3(16, 32), 256>>>(x, W2, W1, g1, be1);
    k_fin2<<<16, 256>>>(g2, be2);
    k_gemm<<<128, 256, GEMM_SMEM>>>(bfc, out);
}

// round 15
// speedup vs baseline: 1.4868x; 1.1159x over previous
#include <cuda_runtime.h>
#include <cuda_fp16.h>
#include <cstdint>

#define BATCH 8192
#define DIM   1024
#define H1V   8
#define H2V   4
#define OUTD  256
#define K2DIM 4096   // DIM*H2
#define EPSV  1e-5f
#define RG1   32
#define RG2   32

// ---------------- scratch (device globals; no allocation) ----------------
__device__ __half g_h2[(size_t)BATCH * K2DIM];   // 64 MB, h2 pre-BN in fp16
// Wfc pre-swizzled into mma.m16n8k16 B-fragment order:
// entry i: kt = i>>10, nt = (i>>5)&31, lane = i&31
//   .x = half2( Wfc[n][k0], Wfc[n][k0+1] ), .y = half2( Wfc[n][k0+8], Wfc[n][k0+9] )
//   with n = nt*8 + lane/4, k0 = kt*16 + (lane%4)*2
__device__ uint2  g_wfcB[256 * 32 * 32];         // 2 MB
__device__ float  g_p1s[RG1 * DIM],  g_p1q[RG1 * DIM];
__device__ float  g_p2s[RG2 * K2DIM], g_p2q[RG2 * K2DIM];
__device__ float  g_a2[K2DIM], g_c2[K2DIM];

// ---------------- K1: merged Wfc fragment-swizzle + per-column sums of x ----------------
__global__ void k_pre(const float* __restrict__ x, const float* __restrict__ Wfc) {
    int b = blockIdx.x, t = threadIdx.x;
    if (b < 256) {
        int cg = b & 7, rg = b >> 3;
        int cl = t & 31, rt = t >> 5;
        int d = cg * 128 + cl * 4;
        float4 s = make_float4(0.f, 0.f, 0.f, 0.f);
        float4 q = make_float4(0.f, 0.f, 0.f, 0.f);
        const float4* p = reinterpret_cast<const float4*>(
            x + (size_t)(rg * 256 + rt) * DIM + d);
#pragma unroll 8
        for (int i = 0; i < 32; i++) {
            float4 v = p[(size_t)i * 8 * (DIM / 4)];
            s.x += v.x; q.x = fmaf(v.x, v.x, q.x);
            s.y += v.y; q.y = fmaf(v.y, v.y, q.y);
            s.z += v.z; q.z = fmaf(v.z, v.z, q.z);
            s.w += v.w; q.w = fmaf(v.w, v.w, q.w);
        }
        __shared__ float rs[8][128], rq[8][128];
        rs[rt][cl * 4 + 0] = s.x; rq[rt][cl * 4 + 0] = q.x;
        rs[rt][cl * 4 + 1] = s.y; rq[rt][cl * 4 + 1] = q.y;
        rs[rt][cl * 4 + 2] = s.z; rq[rt][cl * 4 + 2] = q.z;
        rs[rt][cl * 4 + 3] = s.w; rq[rt][cl * 4 + 3] = q.w;
        __syncthreads();
        if (t < 128) {
            float ss = 0.f, qq = 0.f;
#pragma unroll
            for (int r = 0; r < 8; r++) { ss += rs[r][t]; qq += rq[r][t]; }
            g_p1s[rg * DIM + cg * 128 + t] = ss;
            g_p1q[rg * DIM + cg * 128 + t] = qq;
        }
    } else {
        int i = (b - 256) * 256 + t;              // [0, 262144)
        int lane = i & 31, nt = (i >> 5) & 31, kt = i >> 10;
        int n = nt * 8 + (lane >> 2);
        int k0 = kt * 16 + (lane & 3) * 2;
        const float* wr = Wfc + (size_t)n * K2DIM + k0;
        __half2 b0 = __floats2half2_rn(wr[0], wr[1]);
        __half2 b1 = __floats2half2_rn(wr[8], wr[9]);
        uint2 pk;
        pk.x = *reinterpret_cast<uint32_t*>(&b0);
        pk.y = *reinterpret_cast<uint32_t*>(&b1);
        g_wfcB[i] = pk;
    }
}

// ---------------- K2: fin1 prologue + fused y1 -> h2 ----------------
__global__ void __launch_bounds__(256)
k_layer2(const float* __restrict__ x, const float* __restrict__ W2,
         const float* __restrict__ W1, const float* __restrict__ g1,
         const float* __restrict__ be1) {
    int cg = blockIdx.x, rg = blockIdx.y, t = threadIdx.x;
    int dl = t & 63, rt = t >> 6;
    int d = cg * 64 + dl;

    __shared__ float sa[512], sc[512], sw[2048];

    if (t < 64) {
        int dd = cg * 64 + t;
        float s = 0.f, q = 0.f;
#pragma unroll
        for (int r = 0; r < RG1; r++) { s += g_p1s[r * DIM + dd]; q += g_p1q[r * DIM + dd]; }
        float mx = s * (1.f / BATCH);
        float vx = fmaxf(q * (1.f / BATCH) - mx * mx, 0.f);
#pragma unroll
        for (int i = 0; i < H1V; i++) {
            int c = dd * H1V + i;
            float w = W1[c];
            float a = g1[c] * w * rsqrtf(fmaf(w * w, vx, EPSV));
            sa[t * 8 + i] = a;
            sc[t * 8 + i] = be1[c] - a * mx;   // b1 cancels inside BN
        }
    }
    for (int i = t; i < 2048; i += 256) { sw[i] = W2[cg * 2048 + i]; }
    __syncthreads();

    float a1r[8], c1r[8], w2r[4][8];
#pragma unroll
    for (int i = 0; i < 8; i++) { a1r[i] = sa[dl * 8 + i]; c1r[i] = sc[dl * 8 + i]; }
#pragma unroll
    for (int o = 0; o < 4; o++)
#pragma unroll
        for (int i = 0; i < 8; i++) w2r[o][i] = sw[dl * 32 + o * 8 + i];

    float s[4] = {0, 0, 0, 0}, q[4] = {0, 0, 0, 0};
    const int rbase = rg * 256 + rt;

#pragma unroll 1
    for (int it = 0; it < 64; it += 4) {
        float xv[4];
#pragma unroll
        for (int u = 0; u < 4; u++)
            xv[u] = x[(size_t)(rbase + (it + u) * 4) * DIM + d];
#pragma unroll
        for (int u = 0; u < 4; u++) {
            int r = rbase + (it + u) * 4;
            float y[8];
#pragma unroll
            for (int i = 0; i < 8; i++) y[i] = fmaxf(fmaf(a1r[i], xv[u], c1r[i]), 0.f);
            float h[4];
#pragma unroll
            for (int o = 0; o < 4; o++) {
                float acc = 0.f;
#pragma unroll
                for (int i = 0; i < 8; i++) acc = fmaf(w2r[o][i], y[i], acc);
                h[o] = acc;
                s[o] += acc;
                q[o] = fmaf(acc, acc, q[o]);
            }
            __half2 h01 = __floats2half2_rn(h[0], h[1]);
            __half2 h23 = __floats2half2_rn(h[2], h[3]);
            uint2 pk;
            pk.x = *reinterpret_cast<uint32_t*>(&h01);
            pk.y = *reinterpret_cast<uint32_t*>(&h23);
            *reinterpret_cast<uint2*>(g_h2 + (size_t)r * K2DIM + d * 4) = pk;
        }
    }

    __shared__ float red[4][64][8];
#pragma unroll
    for (int o = 0; o < 4; o++) { red[rt][dl][o] = s[o]; red[rt][dl][4 + o] = q[o]; }
    __syncthreads();
    if (t < 64) {
#pragma unroll
        for (int o = 0; o < 4; o++) {
            float ss = red[0][t][o] + red[1][t][o] + red[2][t][o] + red[3][t][o];
            float qq = red[0][t][4 + o] + red[1][t][4 + o] + red[2][t][4 + o] + red[3][t][4 + o];
            int c = (cg * 64 + t) * 4 + o;
            g_p2s[rg * K2DIM + c] = ss;
            g_p2q[rg * K2DIM + c] = qq;
        }
    }
}

// ---------------- K3: finalize layer-2 affine coefficients ----------------
__global__ void k_fin2(const float* __restrict__ g2, const float* __restrict__ be2) {
    int c = blockIdx.x * 256 + threadIdx.x;
    float s = 0.f, q = 0.f;
#pragma unroll
    for (int r = 0; r < RG2; r++) { s += g_p2s[r * K2DIM + c]; q += g_p2q[r * K2DIM + c]; }
    float mu = s * (1.f / BATCH);
    float var = fmaxf(q * (1.f / BATCH) - mu * mu, 0.f);
    float a = g2[c] * rsqrtf(var + EPSV);
    g_a2[c] = a;
    g_c2[c] = be2[c] - a * mu;
}

// ---------------- K4: out = relu(a2*h2+c2) @ Wfc^T + bfc ----------------
// M_TILE=32, grid 256 (single full wave, 2 CTAs/SM). Warp = 32m x 32n tile.
__device__ __forceinline__ void ldsm_x4(uint32_t& r0, uint32_t& r1, uint32_t& r2, uint32_t& r3,
                                        uint32_t addr) {
    asm volatile("ldmatrix.sync.aligned.m8n8.x4.shared.b16 {%0,%1,%2,%3}, [%4];"
                 : "=r"(r0), "=r"(r1), "=r"(r2), "=r"(r3) : "r"(addr));
}
__device__ __forceinline__ void mma16816(float* c, const uint32_t a[4], uint32_t b0, uint32_t b1) {
    asm volatile(
        "mma.sync.aligned.m16n8k16.row.col.f32.f16.f16.f32 "
        "{%0,%1,%2,%3},{%4,%5,%6,%7},{%8,%9},{%0,%1,%2,%3};"
        : "+f"(c[0]), "+f"(c[1]), "+f"(c[2]), "+f"(c[3])
        : "r"(a[0]), "r"(a[1]), "r"(a[2]), "r"(a[3]), "r"(b0), "r"(b1));
}

#define AS_ELEMS (2 * 32 * 72)                       // 2 stages x 32 rows x 72 halves
#define GEMM_SMEM (AS_ELEMS * 2 + 2 * K2DIM * 4)     // 9216 + 32768 = 41984 B

__global__ void __launch_bounds__(256, 2)
k_gemm(const float* __restrict__ bfc, float* __restrict__ out) {
    extern __shared__ char smraw[];
    __half* As = reinterpret_cast<__half*>(smraw);       // [2][32][72]
    float* a2s = reinterpret_cast<float*>(As + AS_ELEMS);
    float* c2s = a2s + K2DIM;

    const int t = threadIdx.x;
    const int bm = blockIdx.x * 32;
    const int warp = t >> 5, lane = t & 31;
    const int wn = warp;                                 // warp tile: 32(m) x 32(n)

    for (int i = t; i < K2DIM; i += 256) { a2s[i] = g_a2[i]; c2s[i] = g_c2[i]; }

    const int arow = t >> 3, akoff = (t & 7) * 8;        // A: 8 threads/row, 8 halves each
    const __half* Agp = g_h2 + (size_t)(bm + arow) * K2DIM + akoff;

    float acc[2][4][4];
#pragma unroll
    for (int a = 0; a < 2; a++)
#pragma unroll
        for (int b = 0; b < 4; b++)
#pragma unroll
            for (int c = 0; c < 4; c++) acc[a][b][c] = 0.f;

    uint4 av;

    auto store_chunk = [&](int buf, int kbase) {
        uint4 v = av;
        __half2* hp = reinterpret_cast<__half2*>(&v);
        int kb = kbase + akoff;
#pragma unroll
        for (int e = 0; e < 4; e++) {
            float2 f = __half22float2(hp[e]);
            int k = kb + e * 2;
            f.x = fmaxf(fmaf(a2s[k], f.x, c2s[k]), 0.f);
            f.y = fmaxf(fmaf(a2s[k + 1], f.y, c2s[k + 1]), 0.f);
            hp[e] = __floats2half2_rn(f.x, f.y);
        }
        *reinterpret_cast<uint4*>(As + buf * (32 * 72) + arow * 72 + akoff) = v;
    };

    // B fragment stream: stage s = 16-k tile index (0..255); warp covers nt wn*4..wn*4+3
    const uint2* Bbase = g_wfcB + (wn * 4) * 32 + lane;
    uint2 bb[2][4];
#pragma unroll
    for (int nt = 0; nt < 4; nt++) bb[0][nt] = Bbase[nt * 32];   // s = 0

    // prologue: A chunk 0
    av = *reinterpret_cast<const uint4*>(Agp);
    __syncthreads();                 // a2s/c2s ready
    store_chunk(0, 0);
    __syncthreads();

    const int a_lrow = lane & 15;
    const int a_ksel = ((lane >> 4) & 1) << 3;

    for (int kc = 0; kc < 64; kc++) {
        int cur = kc & 1;
        if (kc < 63)
            av = *reinterpret_cast<const uint4*>(Agp + (kc + 1) * 64);
        const __half* Ac = As + cur * (32 * 72);
#pragma unroll
        for (int ks = 0; ks < 4; ks++) {
            int s = kc * 4 + ks;
            int bcur = s & 1;
            if (s < 255) {
                const uint2* bp = Bbase + (size_t)(s + 1) * 1024;
#pragma unroll
                for (int nt = 0; nt < 4; nt++) bb[bcur ^ 1][nt] = bp[nt * 32];
            }
            int kb = ks * 16;
            uint32_t af[2][4];
#pragma unroll
            for (int mt = 0; mt < 2; mt++) {
                int row = mt * 16 + a_lrow;
                uint32_t addr = (uint32_t)__cvta_generic_to_shared(Ac + row * 72 + kb + a_ksel);
                ldsm_x4(af[mt][0], af[mt][1], af[mt][2], af[mt][3], addr);
            }
#pragma unroll
            for (int nt = 0; nt < 4; nt++) {
                uint32_t b0 = bb[bcur][nt].x, b1 = bb[bcur][nt].y;
#pragma unroll
                for (int mt = 0; mt < 2; mt++)
                    mma16816(acc[mt][nt], af[mt], b0, b1);
            }
        }
        if (kc < 63) store_chunk(1 - cur, (kc + 1) * 64);
        __syncthreads();
    }

    // epilogue
#pragma unroll
    for (int mt = 0; mt < 2; mt++) {
        int r0 = bm + mt * 16 + (lane >> 2);
#pragma unroll
        for (int nt = 0; nt < 4; nt++) {
            int cc = wn * 32 + nt * 8 + ((lane & 3) << 1);
            float bl = __ldg(bfc + cc), bh = __ldg(bfc + cc + 1);
            float2 v0 = make_float2(acc[mt][nt][0] + bl, acc[mt][nt][1] + bh);
            float2 v1 = make_float2(acc[mt][nt][2] + bl, acc[mt][nt][3] + bh);
            *reinterpret_cast<float2*>(out + (size_t)r0 * OUTD + cc) = v0;
            *reinterpret_cast<float2*>(out + (size_t)(r0 + 8) * OUTD + cc) = v1;
        }
    }
}

// ---------------- launch ----------------
extern "C" void kernel_launch(void* const* d_in, const int* in_sizes, int n_in,
                              void* d_out, int out_size) {
    const float* x   = (const float*)d_in[0];
    const float* W1  = (const float*)d_in[1];
    const float* g1  = (const float*)d_in[3];
    const float* be1 = (const float*)d_in[4];
    const float* W2  = (const float*)d_in[5];
    const float* g2  = (const float*)d_in[7];
    const float* be2 = (const float*)d_in[8];
    const float* Wfc = (const float*)d_in[9];
    const float* bfc = (const float*)d_in[10];
    float* out = (float*)d_out;

    cudaFuncSetAttribute(k_gemm, cudaFuncAttributeMaxDynamicSharedMemorySize, GEMM_SMEM);

    k_pre<<<1280, 256>>>(x, Wfc);
    k_layer2<<<dim3(16, 32), 256>>>(x, W2, W1, g1, be1);
    k_fin2<<<16, 256>>>(g2, be2);
    k_gemm<<<256, 256, GEMM_SMEM>>>(bfc, out);
}

// round 17
// speedup vs baseline: 1.7329x; 1.1655x over previous
#include <cuda_runtime.h>
#include <cuda_fp16.h>
#include <cstdint>

#define BATCH 8192
#define DIM   1024
#define H1V   8
#define H2V   4
#define OUTD  256
#define K2DIM 4096   // DIM*H2
#define EPSV  1e-5f
#define RG1   32
#define RG2   32

// ---------------- scratch (device globals; no allocation) ----------------
__device__ __half g_h2[(size_t)BATCH * K2DIM];   // 64 MB, h2 pre-BN in fp16
// Wfc pre-swizzled into mma.m16n8k16 B-fragment order:
// entry i: kt = i>>10, nt = (i>>5)&31, lane = i&31
//   .x = half2( Wfc[n][k0], Wfc[n][k0+1] ), .y = half2( Wfc[n][k0+8], Wfc[n][k0+9] )
//   with n = nt*8 + lane/4, k0 = kt*16 + (lane%4)*2
__device__ uint2  g_wfcB[256 * 32 * 32];         // 2 MB
__device__ float  g_p1s[RG1 * DIM],  g_p1q[RG1 * DIM];
__device__ float  g_p2s[RG2 * K2DIM], g_p2q[RG2 * K2DIM];
__device__ float  g_a2[K2DIM], g_c2[K2DIM];

// ---------------- K1: merged Wfc fragment-swizzle + per-column sums of x ----------------
__global__ void k_pre(const float* __restrict__ x, const float* __restrict__ Wfc) {
    int b = blockIdx.x, t = threadIdx.x;
    if (b < 256) {
        int cg = b & 7, rg = b >> 3;
        int cl = t & 31, rt = t >> 5;
        int d = cg * 128 + cl * 4;
        float4 s = make_float4(0.f, 0.f, 0.f, 0.f);
        float4 q = make_float4(0.f, 0.f, 0.f, 0.f);
        const float4* p = reinterpret_cast<const float4*>(
            x + (size_t)(rg * 256 + rt) * DIM + d);
#pragma unroll 8
        for (int i = 0; i < 32; i++) {
            float4 v = p[(size_t)i * 8 * (DIM / 4)];
            s.x += v.x; q.x = fmaf(v.x, v.x, q.x);
            s.y += v.y; q.y = fmaf(v.y, v.y, q.y);
            s.z += v.z; q.z = fmaf(v.z, v.z, q.z);
            s.w += v.w; q.w = fmaf(v.w, v.w, q.w);
        }
        __shared__ float rs[8][128], rq[8][128];
        rs[rt][cl * 4 + 0] = s.x; rq[rt][cl * 4 + 0] = q.x;
        rs[rt][cl * 4 + 1] = s.y; rq[rt][cl * 4 + 1] = q.y;
        rs[rt][cl * 4 + 2] = s.z; rq[rt][cl * 4 + 2] = q.z;
        rs[rt][cl * 4 + 3] = s.w; rq[rt][cl * 4 + 3] = q.w;
        __syncthreads();
        if (t < 128) {
            float ss = 0.f, qq = 0.f;
#pragma unroll
            for (int r = 0; r < 8; r++) { ss += rs[r][t]; qq += rq[r][t]; }
            g_p1s[rg * DIM + cg * 128 + t] = ss;
            g_p1q[rg * DIM + cg * 128 + t] = qq;
        }
    } else {
        int i = (b - 256) * 256 + t;              // [0, 262144)
        int lane = i & 31, nt = (i >> 5) & 31, kt = i >> 10;
        int n = nt * 8 + (lane >> 2);
        int k0 = kt * 16 + (lane & 3) * 2;
        const float* wr = Wfc + (size_t)n * K2DIM + k0;
        __half2 b0 = __floats2half2_rn(wr[0], wr[1]);
        __half2 b1 = __floats2half2_rn(wr[8], wr[9]);
        uint2 pk;
        pk.x = *reinterpret_cast<uint32_t*>(&b0);
        pk.y = *reinterpret_cast<uint32_t*>(&b1);
        g_wfcB[i] = pk;
    }
}

// ---------------- K2: fin1 prologue + fused y1 -> h2 ----------------
__global__ void __launch_bounds__(256)
k_layer2(const float* __restrict__ x, const float* __restrict__ W2,
         const float* __restrict__ W1, const float* __restrict__ g1,
         const float* __restrict__ be1) {
    int cg = blockIdx.x, rg = blockIdx.y, t = threadIdx.x;
    int dl = t & 63, rt = t >> 6;
    int d = cg * 64 + dl;

    __shared__ float sa[512], sc[512], sw[2048];

    if (t < 64) {
        int dd = cg * 64 + t;
        float s = 0.f, q = 0.f;
#pragma unroll
        for (int r = 0; r < RG1; r++) { s += g_p1s[r * DIM + dd]; q += g_p1q[r * DIM + dd]; }
        float mx = s * (1.f / BATCH);
        float vx = fmaxf(q * (1.f / BATCH) - mx * mx, 0.f);
#pragma unroll
        for (int i = 0; i < H1V; i++) {
            int c = dd * H1V + i;
            float w = W1[c];
            float a = g1[c] * w * rsqrtf(fmaf(w * w, vx, EPSV));
            sa[t * 8 + i] = a;
            sc[t * 8 + i] = be1[c] - a * mx;   // b1 cancels inside BN
        }
    }
    for (int i = t; i < 2048; i += 256) { sw[i] = W2[cg * 2048 + i]; }
    __syncthreads();

    float a1r[8], c1r[8], w2r[4][8];
#pragma unroll
    for (int i = 0; i < 8; i++) { a1r[i] = sa[dl * 8 + i]; c1r[i] = sc[dl * 8 + i]; }
#pragma unroll
    for (int o = 0; o < 4; o++)
#pragma unroll
        for (int i = 0; i < 8; i++) w2r[o][i] = sw[dl * 32 + o * 8 + i];

    float s[4] = {0, 0, 0, 0}, q[4] = {0, 0, 0, 0};
    const int rbase = rg * 256 + rt;

#pragma unroll 1
    for (int it = 0; it < 64; it += 4) {
        float xv[4];
#pragma unroll
        for (int u = 0; u < 4; u++)
            xv[u] = x[(size_t)(rbase + (it + u) * 4) * DIM + d];
#pragma unroll
        for (int u = 0; u < 4; u++) {
            int r = rbase + (it + u) * 4;
            float y[8];
#pragma unroll
            for (int i = 0; i < 8; i++) y[i] = fmaxf(fmaf(a1r[i], xv[u], c1r[i]), 0.f);
            float h[4];
#pragma unroll
            for (int o = 0; o < 4; o++) {
                float acc = 0.f;
#pragma unroll
                for (int i = 0; i < 8; i++) acc = fmaf(w2r[o][i], y[i], acc);
                h[o] = acc;
                s[o] += acc;
                q[o] = fmaf(acc, acc, q[o]);
            }
            __half2 h01 = __floats2half2_rn(h[0], h[1]);
            __half2 h23 = __floats2half2_rn(h[2], h[3]);
            uint2 pk;
            pk.x = *reinterpret_cast<uint32_t*>(&h01);
            pk.y = *reinterpret_cast<uint32_t*>(&h23);
            *reinterpret_cast<uint2*>(g_h2 + (size_t)r * K2DIM + d * 4) = pk;
        }
    }

    __shared__ float red[4][64][8];
#pragma unroll
    for (int o = 0; o < 4; o++) { red[rt][dl][o] = s[o]; red[rt][dl][4 + o] = q[o]; }
    __syncthreads();
    if (t < 64) {
#pragma unroll
        for (int o = 0; o < 4; o++) {
            float ss = red[0][t][o] + red[1][t][o] + red[2][t][o] + red[3][t][o];
            float qq = red[0][t][4 + o] + red[1][t][4 + o] + red[2][t][4 + o] + red[3][t][4 + o];
            int c = (cg * 64 + t) * 4 + o;
            g_p2s[rg * K2DIM + c] = ss;
            g_p2q[rg * K2DIM + c] = qq;
        }
    }
}

// ---------------- K3: finalize layer-2 affine coefficients ----------------
__global__ void k_fin2(const float* __restrict__ g2, const float* __restrict__ be2) {
    int c = blockIdx.x * 256 + threadIdx.x;
    float s = 0.f, q = 0.f;
#pragma unroll
    for (int r = 0; r < RG2; r++) { s += g_p2s[r * K2DIM + c]; q += g_p2q[r * K2DIM + c]; }
    float mu = s * (1.f / BATCH);
    float var = fmaxf(q * (1.f / BATCH) - mu * mu, 0.f);
    float a = g2[c] * rsqrtf(var + EPSV);
    g_a2[c] = a;
    g_c2[c] = be2[c] - a * mu;
}

// ---------------- K4: out = relu(a2*h2+c2) @ Wfc^T + bfc ----------------
// M_TILE=32, grid 256. Warp = 32m x 32n. B prefetch distance 2 (4-buffer ring).
__device__ __forceinline__ void ldsm_x4(uint32_t& r0, uint32_t& r1, uint32_t& r2, uint32_t& r3,
                                        uint32_t addr) {
    asm volatile("ldmatrix.sync.aligned.m8n8.x4.shared.b16 {%0,%1,%2,%3}, [%4];"
                 : "=r"(r0), "=r"(r1), "=r"(r2), "=r"(r3) : "r"(addr));
}
__device__ __forceinline__ void mma16816(float* c, const uint32_t a[4], uint32_t b0, uint32_t b1) {
    asm volatile(
        "mma.sync.aligned.m16n8k16.row.col.f32.f16.f16.f32 "
        "{%0,%1,%2,%3},{%4,%5,%6,%7},{%8,%9},{%0,%1,%2,%3};"
        : "+f"(c[0]), "+f"(c[1]), "+f"(c[2]), "+f"(c[3])
        : "r"(a[0]), "r"(a[1]), "r"(a[2]), "r"(a[3]), "r"(b0), "r"(b1));
}

#define AS_ELEMS (2 * 32 * 72)                       // 2 stages x 32 rows x 72 halves
#define GEMM_SMEM (AS_ELEMS * 2 + 2 * K2DIM * 4)     // 9216 + 32768 = 41984 B

__global__ void __launch_bounds__(256, 2)
k_gemm(const float* __restrict__ bfc, float* __restrict__ out) {
    extern __shared__ char smraw[];
    __half* As = reinterpret_cast<__half*>(smraw);       // [2][32][72]
    float* a2s = reinterpret_cast<float*>(As + AS_ELEMS);
    float* c2s = a2s + K2DIM;

    const int t = threadIdx.x;
    const int bm = blockIdx.x * 32;
    const int warp = t >> 5, lane = t & 31;
    const int wn = warp;                                 // warp tile: 32(m) x 32(n)

    for (int i = t; i < K2DIM; i += 256) { a2s[i] = g_a2[i]; c2s[i] = g_c2[i]; }

    const int arow = t >> 3, akoff = (t & 7) * 8;        // A: 8 threads/row, 8 halves each
    const __half* Agp = g_h2 + (size_t)(bm + arow) * K2DIM + akoff;

    float acc[2][4][4];
#pragma unroll
    for (int a = 0; a < 2; a++)
#pragma unroll
        for (int b = 0; b < 4; b++)
#pragma unroll
            for (int c = 0; c < 4; c++) acc[a][b][c] = 0.f;

    uint4 av;

    auto store_chunk = [&](int buf, int kbase) {
        uint4 v = av;
        __half2* hp = reinterpret_cast<__half2*>(&v);
        int kb = kbase + akoff;
#pragma unroll
        for (int e = 0; e < 4; e++) {
            float2 f = __half22float2(hp[e]);
            int k = kb + e * 2;
            f.x = fmaxf(fmaf(a2s[k], f.x, c2s[k]), 0.f);
            f.y = fmaxf(fmaf(a2s[k + 1], f.y, c2s[k + 1]), 0.f);
            hp[e] = __floats2half2_rn(f.x, f.y);
        }
        *reinterpret_cast<uint4*>(As + buf * (32 * 72) + arow * 72 + akoff) = v;
    };

    // B fragment ring: stage s = 16-k tile index (0..255); s&3 == ks (kc*4 aligned).
    // At stage s: consume bb[s&3]; issue load for s+2 into bb[(s+2)&3].
    const uint2* Bbase = g_wfcB + (wn * 4) * 32 + lane;
    uint2 bb[4][4];
#pragma unroll
    for (int nt = 0; nt < 4; nt++) bb[0][nt] = Bbase[nt * 32];                    // s = 0
#pragma unroll
    for (int nt = 0; nt < 4; nt++) bb[1][nt] = Bbase[(size_t)1024 + nt * 32];     // s = 1

    // prologue: A chunk 0
    av = *reinterpret_cast<const uint4*>(Agp);
    __syncthreads();                 // a2s/c2s ready
    store_chunk(0, 0);
    __syncthreads();

    const int a_lrow = lane & 15;
    const int a_ksel = ((lane >> 4) & 1) << 3;

    for (int kc = 0; kc < 64; kc++) {
        int cur = kc & 1;
        if (kc < 63)
            av = *reinterpret_cast<const uint4*>(Agp + (kc + 1) * 64);
        const __half* Ac = As + cur * (32 * 72);
#pragma unroll
        for (int ks = 0; ks < 4; ks++) {
            int s = kc * 4 + ks;
            // prefetch B for stage s+2 (distance-2: covers L2 latency)
            if (s < 254) {
                const uint2* bp = Bbase + (size_t)(s + 2) * 1024;
#pragma unroll
                for (int nt = 0; nt < 4; nt++) bb[(ks + 2) & 3][nt] = bp[nt * 32];
            }
            int kb = ks * 16;
            uint32_t af[2][4];
#pragma unroll
            for (int mt = 0; mt < 2; mt++) {
                int row = mt * 16 + a_lrow;
                uint32_t addr = (uint32_t)__cvta_generic_to_shared(Ac + row * 72 + kb + a_ksel);
                ldsm_x4(af[mt][0], af[mt][1], af[mt][2], af[mt][3], addr);
            }
#pragma unroll
            for (int nt = 0; nt < 4; nt++) {
                uint32_t b0 = bb[ks][nt].x, b1 = bb[ks][nt].y;
#pragma unroll
                for (int mt = 0; mt < 2; mt++)
                    mma16816(acc[mt][nt], af[mt], b0, b1);
            }
        }
        if (kc < 63) store_chunk(1 - cur, (kc + 1) * 64);
        __syncthreads();
    }

    // epilogue
#pragma unroll
    for (int mt = 0; mt < 2; mt++) {
        int r0 = bm + mt * 16 + (lane >> 2);
#pragma unroll
        for (int nt = 0; nt < 4; nt++) {
            int cc = wn * 32 + nt * 8 + ((lane & 3) << 1);
            float bl = __ldg(bfc + cc), bh = __ldg(bfc + cc + 1);
            float2 v0 = make_float2(acc[mt][nt][0] + bl, acc[mt][nt][1] + bh);
            float2 v1 = make_float2(acc[mt][nt][2] + bl, acc[mt][nt][3] + bh);
            *reinterpret_cast<float2*>(out + (size_t)r0 * OUTD + cc) = v0;
            *reinterpret_cast<float2*>(out + (size_t)(r0 + 8) * OUTD + cc) = v1;
        }
    }
}

// ---------------- launch ----------------
extern "C" void kernel_launch(void* const* d_in, const int* in_sizes, int n_in,
                              void* d_out, int out_size) {
    const float* x   = (const float*)d_in[0];
    const float* W1  = (const float*)d_in[1];
    const float* g1  = (const float*)d_in[3];
    const float* be1 = (const float*)d_in[4];
    const float* W2  = (const float*)d_in[5];
    const float* g2  = (const float*)d_in[7];
    const float* be2 = (const float*)d_in[8];
    const float* Wfc = (const float*)d_in[9];
    const float* bfc = (const float*)d_in[10];
    float* out = (float*)d_out;

    cudaFuncSetAttribute(k_gemm, cudaFuncAttributeMaxDynamicSharedMemorySize, GEMM_SMEM);

    k_pre<<<1280, 256>>>(x, Wfc);
    k_layer2<<<dim3(16, 32), 256>>>(x, W2, W1, g1, be1);
    k_fin2<<<16, 256>>>(g2, be2);
    k_gemm<<<256, 256, GEMM_SMEM>>>(bfc, out);
}